// round 16
// baseline (speedup 1.0000x reference)
#include <cuda_runtime.h>
#include <cuda_bf16.h>
#include <cstdint>

#define MAIN_BLOCKS 1184
#define TPB         256

// Device-global scratch (no allocations). All state self-resets every launch
// (last block restores it after use) -> deterministic, graph-safe.
__device__ unsigned g_act_rng  = 0u;
__device__ unsigned g_mcnt     = 0u;
__device__ unsigned g_packmin  = 0xFFFFFFFFu;
__device__ unsigned g_packmax  = 0u;

// ---------------------------------------------------------------------------
// Robust small-integer scalar decode (int32/int64/float32/float64).
// ---------------------------------------------------------------------------
__device__ __forceinline__ int decode_scalar(const int* p, int dflt) {
    if (p == nullptr) return dflt;
    int w0 = p[0];
    if (w0 >= -1000000 && w0 <= 1000000) {
        if (w0 != 0) return w0;
        int w1 = p[1];
        if (w1 == 0) return 0;
        double d = __hiloint2double(w1, w0);
        if (d >= -1e6 && d <= 1e6) return (int)d;
        return 0;
    }
    float f = __int_as_float(w0);
    if (f >= -1e6f && f <= 1e6f) return (int)f;
    int w1 = p[1];
    double d = __hiloint2double(w1, w0);
    if (d >= -1e6 && d <= 1e6) return (int)d;
    return dflt;
}

// Transform descriptor: pack = mode | (shift << 2)
//   mode 0 = zeros (bw==0), 1 = int8-wrap trunc (shift<1), 2 = psto(shift)
__device__ __forceinline__ unsigned make_pack(unsigned rng, int mu) {
    if (rng == 0u) return 0u;
    int bw = (int)ceilf(log2f(fmaxf((float)rng, 1.0f)));
    int shift = bw - mu;
    if (shift < 1) return 1u;
    return 2u | ((unsigned)shift << 2);
}

__device__ __forceinline__ unsigned max4abs(int4 v) {
    unsigned a0 = (unsigned)(v.x < 0 ? -v.x : v.x);
    unsigned a1 = (unsigned)(v.y < 0 ? -v.y : v.y);
    unsigned a2 = (unsigned)(v.z < 0 ? -v.z : v.z);
    unsigned a3 = (unsigned)(v.w < 0 ? -v.w : v.w);
    return max(max(a0, a1), max(a2, a3));
}

// Apply with hoisted psto constants (mask/hmask/oddm/hs precomputed).
__device__ __forceinline__ void uw_apply_pre(
    int4 gv, int4 wv, int mode, int s, int hs, int mask, int hmask, int oddm,
    float4& ow, float4& og)
{
    int gx[4] = { gv.x, gv.y, gv.z, gv.w };
    int wi[4] = { wv.x, wv.y, wv.z, wv.w };
    float o_g[4], o_w[4];
#pragma unroll
    for (int k = 0; k < 4; k++) {
        int gq;
        if (mode == 0)      gq = 0;
        else if (mode == 1) gq = (int)(signed char)gx[k];   // wraps like astype(int8)
        else {
            int x     = gx[k];
            int rt    = x >> s;
            int prob  = x & mask;            // non-negative floor remainder
            int qprob = prob >> hs;
            int prn   = (prob & hmask) * oddm;
            int sgn   = (x > 0) - (x < 0);
            int dec   = (qprob <= prn) ? 0 : sgn;
            gq = min(127, max(-127, rt + dec));
        }
        int nw = wi[k] - gq;
        nw = min(127, max(-127, nw));
        o_g[k] = (float)gq;
        o_w[k] = (float)nw;
    }
    ow = make_float4(o_w[0], o_w[1], o_w[2], o_w[3]);
    og = make_float4(o_g[0], o_g[1], o_g[2], o_g[3]);
}

__device__ __forceinline__ unsigned block_reduce_max256(unsigned m, unsigned* s_red) {
    m = __reduce_max_sync(0xffffffffu, m);
    int lane = threadIdx.x & 31;
    int wid  = threadIdx.x >> 5;
    if (lane == 0) s_red[wid] = m;
    __syncthreads();
    unsigned v = 0u;
    if (wid == 0) {
        v = (lane < (int)(blockDim.x >> 5)) ? s_red[lane] : 0u;
        v = __reduce_max_sync(0xffffffffu, v);
    }
    return v;  // valid in warp 0
}

// ---------------------------------------------------------------------------
// SINGLE fused kernel, per-block self-guess + in-kernel verification.
// Lean 2-way batched loop; prologue samples WITHOUT holding loads across the
// barrier (main loop re-reads from L1) to minimize register pressure.
// ---------------------------------------------------------------------------
__global__ void uw_main_kernel(
    const int4* __restrict__ w4,
    const int4* __restrict__ g4,
    float4* __restrict__ ow4,
    float4* __restrict__ og4,
    const int* __restrict__ p_err_exp,
    const int* __restrict__ p_act_in_exp,
    const int* __restrict__ p_mu,
    float* __restrict__ out_exp,
    long n4)
{
    __shared__ unsigned s_red[32];
    __shared__ unsigned s_pack;
    __shared__ unsigned s_last;
    __shared__ unsigned s_fix;   // actual pack when fixup needed, else ~0

    const long S  = (long)gridDim.x * blockDim.x;
    const long i0 = (long)blockIdx.x * blockDim.x + threadIdx.x;
    int mu = decode_scalar(p_mu, 7);

    // ---- Prologue: sample first 2 batches (loads NOT held; L1 re-serves) ----
    {
        unsigned m = 0u;
        if (i0 < n4)     m = max4abs(__ldg(&g4[i0]));
        if (i0 + S < n4) m = max(m, max4abs(__ldg(&g4[i0 + S])));
        unsigned bm = block_reduce_max256(m, s_red);
        if (threadIdx.x == 0) s_pack = make_pack(bm, mu);
        __syncthreads();
    }
    const unsigned pack = s_pack;
    const int mode  = (int)(pack & 3u);
    const int s     = (int)(pack >> 2);
    const int hs    = s >> 1;
    const int mask  = (1 << s) - 1;
    const int hmask = (1 << hs) - 1;
    const int oddm  = 1 + (s & 1);

    // ---- Main stream: 2-way batched ----
    unsigned m = 0u;
    long i = i0;
    for (; i + S < n4; i += 2 * S) {
        int4 ga = __ldg(&g4[i]);
        int4 gb = __ldg(&g4[i + S]);
        int4 wa = __ldg(&w4[i]);
        int4 wb = __ldg(&w4[i + S]);
        m = max(m, max(max4abs(ga), max4abs(gb)));
        float4 ow, og;
        uw_apply_pre(ga, wa, mode, s, hs, mask, hmask, oddm, ow, og);
        ow4[i] = ow; og4[i] = og;
        uw_apply_pre(gb, wb, mode, s, hs, mask, hmask, oddm, ow, og);
        ow4[i + S] = ow; og4[i + S] = og;
    }
    for (; i < n4; i += S) {
        int4 gv = __ldg(&g4[i]);
        int4 wv = __ldg(&w4[i]);
        m = max(m, max4abs(gv));
        float4 ow, og;
        uw_apply_pre(gv, wv, mode, s, hs, mask, hmask, oddm, ow, og);
        ow4[i] = ow; og4[i] = og;
    }

    // ---- Epilogue: publish true max + vote; last block verifies ----
    unsigned bm = block_reduce_max256(m, s_red);
    if (threadIdx.x == 0) {
        atomicMax(&g_act_rng, bm);
        if (i0 < n4) {                       // only blocks that did work vote
            atomicMin(&g_packmin, pack);
            atomicMax(&g_packmax, pack);
        }
        __threadfence();
        unsigned t = atomicAdd(&g_mcnt, 1u);
        s_last = (t == (unsigned)(gridDim.x - 1)) ? 1u : 0u;
    }
    __syncthreads();
    if (s_last) {
        if (threadIdx.x == 0) {
            unsigned rng  = atomicAdd(&g_act_rng, 0u);
            unsigned pmin = atomicAdd(&g_packmin, 0u);
            unsigned pmax = atomicAdd(&g_packmax, 0u);
            unsigned act  = make_pack(rng, mu);
            s_fix = (pmin != act || pmax != act) ? act : 0xFFFFFFFFu;
            int amode = (int)(act & 3u);
            int gs    = (amode == 2) ? (int)(act >> 2) : 0;
            int ee = decode_scalar(p_err_exp, -10);
            int ae = decode_scalar(p_act_in_exp, -7);
            *out_exp = (float)(ee + gs + ae);
            // Self-reset for next launch.
            g_mcnt    = 0u;
            g_act_rng = 0u;
            g_packmin = 0xFFFFFFFFu;
            g_packmax = 0u;
        }
        __syncthreads();
        unsigned fixpack = s_fix;
        if (fixpack != 0xFFFFFFFFu) {
            // Astronomically rare slow path: this block alone rewrites all
            // outputs with the actual transform. Correct for ANY input.
            int fmode  = (int)(fixpack & 3u);
            int fsv    = (int)(fixpack >> 2);
            int fhs    = fsv >> 1;
            int fmask  = (1 << fsv) - 1;
            int fhmask = (1 << fhs) - 1;
            int foddm  = 1 + (fsv & 1);
            for (long j = threadIdx.x; j < n4; j += blockDim.x) {
                int4 gv = __ldg(&g4[j]);
                int4 wv = __ldg(&w4[j]);
                float4 ow, og;
                uw_apply_pre(gv, wv, fmode, fsv, fhs, fmask, fhmask, foddm, ow, og);
                ow4[j] = ow;
                og4[j] = og;
            }
        }
    }
}

// ---------------------------------------------------------------------------
// Launch. Inputs: weight int32[N] (promoted int8), grad int32[N],
// err_exp, act_in_exp, mu (int32 scalars).
// Output: float32[2N+1] = concat(new_weight, grad, grad_exp).
// ---------------------------------------------------------------------------
extern "C" void kernel_launch(void* const* d_in, const int* in_sizes, int n_in,
                              void* d_out, int out_size)
{
    const int4* w4 = (const int4*)d_in[0];
    const int4* g4 = (const int4*)d_in[1];
    const int* p_err = (n_in > 2) ? (const int*)d_in[2] : nullptr;
    const int* p_act = (n_in > 3) ? (const int*)d_in[3] : nullptr;
    const int* p_mu  = (n_in > 4) ? (const int*)d_in[4] : nullptr;

    long N  = (long)in_sizes[0];
    long n4 = N >> 2;

    float* out   = (float*)d_out;
    float4* ow4  = (float4*)out;
    float4* og4  = (float4*)(out + N);
    float* out_e = out + 2 * N;

    uw_main_kernel<<<MAIN_BLOCKS, TPB>>>(w4, g4, ow4, og4,
                                         p_err, p_act, p_mu, out_e, n4);
}

// round 17
// speedup vs baseline: 1.0020x; 1.0020x over previous
#include <cuda_runtime.h>
#include <cuda_bf16.h>
#include <cstdint>

#define MAIN_BLOCKS 1184
#define TPB         256

// Device-global scratch (no allocations). All state self-resets every launch
// (last block restores it after use) -> deterministic, graph-safe.
__device__ unsigned g_act_rng  = 0u;
__device__ unsigned g_mcnt     = 0u;
__device__ unsigned g_packmin  = 0xFFFFFFFFu;
__device__ unsigned g_packmax  = 0u;

// ---------------------------------------------------------------------------
// Robust small-integer scalar decode (int32/int64/float32/float64).
// ---------------------------------------------------------------------------
__device__ __forceinline__ int decode_scalar(const int* p, int dflt) {
    if (p == nullptr) return dflt;
    int w0 = p[0];
    if (w0 >= -1000000 && w0 <= 1000000) {
        if (w0 != 0) return w0;
        int w1 = p[1];
        if (w1 == 0) return 0;
        double d = __hiloint2double(w1, w0);
        if (d >= -1e6 && d <= 1e6) return (int)d;
        return 0;
    }
    float f = __int_as_float(w0);
    if (f >= -1e6f && f <= 1e6f) return (int)f;
    int w1 = p[1];
    double d = __hiloint2double(w1, w0);
    if (d >= -1e6 && d <= 1e6) return (int)d;
    return dflt;
}

// Transform descriptor: pack = mode | (shift << 2)
//   mode 0 = zeros (bw==0), 1 = int8-wrap trunc (shift<1), 2 = psto(shift)
__device__ __forceinline__ unsigned make_pack(unsigned rng, int mu) {
    if (rng == 0u) return 0u;
    int bw = (int)ceilf(log2f(fmaxf((float)rng, 1.0f)));
    int shift = bw - mu;
    if (shift < 1) return 1u;
    return 2u | ((unsigned)shift << 2);
}

__device__ __forceinline__ unsigned max4abs(int4 v) {
    unsigned a0 = (unsigned)(v.x < 0 ? -v.x : v.x);
    unsigned a1 = (unsigned)(v.y < 0 ? -v.y : v.y);
    unsigned a2 = (unsigned)(v.z < 0 ? -v.z : v.z);
    unsigned a3 = (unsigned)(v.w < 0 ? -v.w : v.w);
    return max(max(a0, a1), max(a2, a3));
}

// Apply with hoisted psto constants (mask/hmask/oddm/hs precomputed).
__device__ __forceinline__ void uw_apply_pre(
    int4 gv, int4 wv, int mode, int s, int hs, int mask, int hmask, int oddm,
    float4& ow, float4& og)
{
    int gx[4] = { gv.x, gv.y, gv.z, gv.w };
    int wi[4] = { wv.x, wv.y, wv.z, wv.w };
    float o_g[4], o_w[4];
#pragma unroll
    for (int k = 0; k < 4; k++) {
        int gq;
        if (mode == 0)      gq = 0;
        else if (mode == 1) gq = (int)(signed char)gx[k];   // wraps like astype(int8)
        else {
            int x     = gx[k];
            int rt    = x >> s;
            int prob  = x & mask;            // non-negative floor remainder
            int qprob = prob >> hs;
            int prn   = (prob & hmask) * oddm;
            int sgn   = (x > 0) - (x < 0);
            int dec   = (qprob <= prn) ? 0 : sgn;
            gq = min(127, max(-127, rt + dec));
        }
        int nw = wi[k] - gq;
        nw = min(127, max(-127, nw));
        o_g[k] = (float)gq;
        o_w[k] = (float)nw;
    }
    ow = make_float4(o_w[0], o_w[1], o_w[2], o_w[3]);
    og = make_float4(o_g[0], o_g[1], o_g[2], o_g[3]);
}

__device__ __forceinline__ unsigned block_reduce_max256(unsigned m, unsigned* s_red) {
    m = __reduce_max_sync(0xffffffffu, m);
    int lane = threadIdx.x & 31;
    int wid  = threadIdx.x >> 5;
    if (lane == 0) s_red[wid] = m;
    __syncthreads();
    unsigned v = 0u;
    if (wid == 0) {
        v = (lane < (int)(blockDim.x >> 5)) ? s_red[lane] : 0u;
        v = __reduce_max_sync(0xffffffffu, v);
    }
    return v;  // valid in warp 0
}

// ---------------------------------------------------------------------------
// SINGLE fused kernel, per-block self-guess + in-kernel verification.
// Register-lean prologue (sample-and-discard, L1 re-serves) + 4-way batched
// main loop (8 independent loads in flight) under a 5-CTA/SM reg budget.
// ---------------------------------------------------------------------------
__global__ void __launch_bounds__(TPB, 5) uw_main_kernel(
    const int4* __restrict__ w4,
    const int4* __restrict__ g4,
    float4* __restrict__ ow4,
    float4* __restrict__ og4,
    const int* __restrict__ p_err_exp,
    const int* __restrict__ p_act_in_exp,
    const int* __restrict__ p_mu,
    float* __restrict__ out_exp,
    long n4)
{
    __shared__ unsigned s_red[32];
    __shared__ unsigned s_pack;
    __shared__ unsigned s_last;
    __shared__ unsigned s_fix;   // actual pack when fixup needed, else ~0

    const long S  = (long)gridDim.x * blockDim.x;
    const long i0 = (long)blockIdx.x * blockDim.x + threadIdx.x;
    int mu = decode_scalar(p_mu, 7);

    // ---- Prologue: sample first 2 batches (loads NOT held; L1 re-serves) ----
    {
        unsigned m = 0u;
        if (i0 < n4)     m = max4abs(__ldg(&g4[i0]));
        if (i0 + S < n4) m = max(m, max4abs(__ldg(&g4[i0 + S])));
        unsigned bm = block_reduce_max256(m, s_red);
        if (threadIdx.x == 0) s_pack = make_pack(bm, mu);
        __syncthreads();
    }
    const unsigned pack = s_pack;
    const int mode  = (int)(pack & 3u);
    const int s     = (int)(pack >> 2);
    const int hs    = s >> 1;
    const int mask  = (1 << s) - 1;
    const int hmask = (1 << hs) - 1;
    const int oddm  = 1 + (s & 1);

    // ---- Main stream: 4-way batched (8 independent loads in flight) ----
    unsigned m = 0u;
    long i = i0;
    for (; i + 3 * S < n4; i += 4 * S) {
        int4 a0 = __ldg(&g4[i]);
        int4 a1 = __ldg(&g4[i +     S]);
        int4 a2 = __ldg(&g4[i + 2 * S]);
        int4 a3 = __ldg(&g4[i + 3 * S]);
        int4 b0 = __ldg(&w4[i]);
        int4 b1 = __ldg(&w4[i +     S]);
        int4 b2 = __ldg(&w4[i + 2 * S]);
        int4 b3 = __ldg(&w4[i + 3 * S]);
        m = max(m, max(max(max4abs(a0), max4abs(a1)),
                       max(max4abs(a2), max4abs(a3))));
        float4 ow, og;
        uw_apply_pre(a0, b0, mode, s, hs, mask, hmask, oddm, ow, og);
        ow4[i]         = ow; og4[i]         = og;
        uw_apply_pre(a1, b1, mode, s, hs, mask, hmask, oddm, ow, og);
        ow4[i +     S] = ow; og4[i +     S] = og;
        uw_apply_pre(a2, b2, mode, s, hs, mask, hmask, oddm, ow, og);
        ow4[i + 2 * S] = ow; og4[i + 2 * S] = og;
        uw_apply_pre(a3, b3, mode, s, hs, mask, hmask, oddm, ow, og);
        ow4[i + 3 * S] = ow; og4[i + 3 * S] = og;
    }
    for (; i < n4; i += S) {
        int4 gv = __ldg(&g4[i]);
        int4 wv = __ldg(&w4[i]);
        m = max(m, max4abs(gv));
        float4 ow, og;
        uw_apply_pre(gv, wv, mode, s, hs, mask, hmask, oddm, ow, og);
        ow4[i] = ow; og4[i] = og;
    }

    // ---- Epilogue: publish true max + vote; last block verifies ----
    unsigned bm = block_reduce_max256(m, s_red);
    if (threadIdx.x == 0) {
        atomicMax(&g_act_rng, bm);
        if (i0 < n4) {                       // only blocks that did work vote
            atomicMin(&g_packmin, pack);
            atomicMax(&g_packmax, pack);
        }
        __threadfence();
        unsigned t = atomicAdd(&g_mcnt, 1u);
        s_last = (t == (unsigned)(gridDim.x - 1)) ? 1u : 0u;
    }
    __syncthreads();
    if (s_last) {
        if (threadIdx.x == 0) {
            unsigned rng  = atomicAdd(&g_act_rng, 0u);
            unsigned pmin = atomicAdd(&g_packmin, 0u);
            unsigned pmax = atomicAdd(&g_packmax, 0u);
            unsigned act  = make_pack(rng, mu);
            s_fix = (pmin != act || pmax != act) ? act : 0xFFFFFFFFu;
            int amode = (int)(act & 3u);
            int gs    = (amode == 2) ? (int)(act >> 2) : 0;
            int ee = decode_scalar(p_err_exp, -10);
            int ae = decode_scalar(p_act_in_exp, -7);
            *out_exp = (float)(ee + gs + ae);
            // Self-reset for next launch.
            g_mcnt    = 0u;
            g_act_rng = 0u;
            g_packmin = 0xFFFFFFFFu;
            g_packmax = 0u;
        }
        __syncthreads();
        unsigned fixpack = s_fix;
        if (fixpack != 0xFFFFFFFFu) {
            // Astronomically rare slow path: this block alone rewrites all
            // outputs with the actual transform. Correct for ANY input.
            int fmode  = (int)(fixpack & 3u);
            int fsv    = (int)(fixpack >> 2);
            int fhs    = fsv >> 1;
            int fmask  = (1 << fsv) - 1;
            int fhmask = (1 << fhs) - 1;
            int foddm  = 1 + (fsv & 1);
            for (long j = threadIdx.x; j < n4; j += blockDim.x) {
                int4 gv = __ldg(&g4[j]);
                int4 wv = __ldg(&w4[j]);
                float4 ow, og;
                uw_apply_pre(gv, wv, fmode, fsv, fhs, fmask, fhmask, foddm, ow, og);
                ow4[j] = ow;
                og4[j] = og;
            }
        }
    }
}

// ---------------------------------------------------------------------------
// Launch. Inputs: weight int32[N] (promoted int8), grad int32[N],
// err_exp, act_in_exp, mu (int32 scalars).
// Output: float32[2N+1] = concat(new_weight, grad, grad_exp).
// ---------------------------------------------------------------------------
extern "C" void kernel_launch(void* const* d_in, const int* in_sizes, int n_in,
                              void* d_out, int out_size)
{
    const int4* w4 = (const int4*)d_in[0];
    const int4* g4 = (const int4*)d_in[1];
    const int* p_err = (n_in > 2) ? (const int*)d_in[2] : nullptr;
    const int* p_act = (n_in > 3) ? (const int*)d_in[3] : nullptr;
    const int* p_mu  = (n_in > 4) ? (const int*)d_in[4] : nullptr;

    long N  = (long)in_sizes[0];
    long n4 = N >> 2;

    float* out   = (float*)d_out;
    float4* ow4  = (float4*)out;
    float4* og4  = (float4*)(out + N);
    float* out_e = out + 2 * N;

    uw_main_kernel<<<MAIN_BLOCKS, TPB>>>(w4, g4, ow4, og4,
                                         p_err, p_act, p_mu, out_e, n4);
}